// round 5
// baseline (speedup 1.0000x reference)
#include <cuda_runtime.h>
#include <cstdint>

// ---------------- problem constants ----------------
#define B_    4
#define C_    64
#define NPIX  1024            // 32*32
#define PR    34              // padded rows used (0..33)
#define PSTR  36              // padded row stride in g_a (floats)
#define PLANE (PR * PSTR)     // floats per (b,c) plane
#define S_    16              // K-split factor
#define CCHUNK 4              // channels per split
#define ASTRIDE 40            // As row stride (floats)

// ---------------- scratch (device globals) ----------------
__device__ float g_a1[B_ * C_ * PLANE];          // relu(bn1(x)), zero-padded
__device__ float g_a2[B_ * C_ * PLANE];          // relu(bn2(adder1)), zero-padded
__device__ float g_p1[S_ * B_ * C_ * NPIX];      // adder1 partials (TRUE values)
__device__ float g_p2[S_ * B_ * C_ * NPIX];      // adder2 partials (TRUE values)
__device__ float g_out2[B_ * C_ * NPIX];         // adder2 full output
__device__ float g_s[B_ * C_];                   // channel means

// ---------------- BN + ReLU into zero-padded layout ----------------
// stage==0: input = x, output = g_a1
// stage==1: input = sum(g_p1) (true adder1 output), output = g_a2
__global__ void k_bnpad(const float* __restrict__ xin, int stage,
                        const float* __restrict__ gam,
                        const float* __restrict__ bet,
                        const float* __restrict__ mu,
                        const float* __restrict__ var) {
    int idx = blockIdx.x * blockDim.x + threadIdx.x;
    const int total = B_ * C_ * PLANE;
    if (idx >= total) return;
    float* outp = stage ? g_a2 : g_a1;

    int q  = idx % PSTR;
    int t  = idx / PSTR;
    int r  = t % PR;
    int bc = t / PR;

    float val = 0.f;
    if (r >= 1 && r <= 32 && q >= 1 && q <= 32) {
        int pix = bc * NPIX + (r - 1) * 32 + (q - 1);
        int c = bc & (C_ - 1);
        float inv = gam[c] * rsqrtf(var[c] + 1e-5f);
        float bias = bet[c] - mu[c] * inv;
        float s;
        if (stage) {
            s = 0.f;
#pragma unroll
            for (int sp = 0; sp < S_; sp++)
                s += g_p1[sp * (B_ * C_ * NPIX) + pix];
        } else {
            s = xin[pix];
        }
        val = fmaxf(s * inv + bias, 0.f);
    }
    outp[idx] = val;
}

// ---------------- AdderNet conv via min-identity, K-split ----------------
// sum|a-w| = sumA + sumW - 2*sum min(a,w)
// inner loop: FMNMX (alu pipe) + FADD (fma pipe) -> dual-pipe balanced
// grid: (64 pixel-tiles, 16 k-splits); block: 128 threads (4 warps)
// pixel tile = one image's 2 output rows x 32 cols, all 64 out-ch
// thread tile = 8 px (2 rows x cols pcol0+8i) x 4 out-ch (og*4..og*4+3)
__global__ __launch_bounds__(128, 7) void k_adder(int stage,
                                                  const float* __restrict__ w) {
    __shared__ float As[CCHUNK * 4 * ASTRIDE];   // staged a, 2.5 KB
    __shared__ float Bs[CCHUNK * 9 * 64];        // weights, 9 KB
    __shared__ float Rs[CCHUNK * 4 * 32];        // 3-tap row sums, 2 KB
    __shared__ float sAs[64];                    // window sums per pixel
    __shared__ float sWs[64];                    // weight sums per out-ch

    const float* apad = stage ? g_a2 : g_a1;
    float*       part = stage ? g_p2 : g_p1;

    int tid  = threadIdx.x;
    int bx   = blockIdx.x;           // 0..63
    int sp   = blockIdx.y;           // 0..15 (k-split)
    int b    = bx >> 4;
    int row0 = (bx & 15) * 2;        // output rows row0, row0+1
    int c0   = sp * CCHUNK;

    int og    = tid >> 3;            // 0..15 -> out channels og*4..og*4+3
    int pcol0 = tid & 7;             // 0..7

    // stage A: 4 channels x 4 padded rows x ASTRIDE cols (zero-fill tail)
    const float* ap = apad + (b * C_ + c0) * PLANE;
    for (int i = tid; i < CCHUNK * 4 * ASTRIDE; i += 128) {
        int cc  = i / (4 * ASTRIDE);
        int rem = i - cc * (4 * ASTRIDE);
        int r   = rem / ASTRIDE;
        int q   = rem - r * ASTRIDE;
        As[i] = (q < PSTR) ? ap[cc * PLANE + (row0 + r) * PSTR + q] : 0.f;
    }
    // stage B: weights, Bs[k][o] = w[o][c0+cc][kh][kw]
    for (int i = tid; i < CCHUNK * 9 * 64; i += 128) {
        int k  = i >> 6;                     // 0..35
        int o  = i & 63;
        int cc = k / 9;
        int t9 = k - cc * 9;
        Bs[k * 64 + o] = w[(o * C_ + c0 + cc) * 9 + t9];
    }
    __syncthreads();

    // phase 1: horizontal 3-tap row sums + per-oc weight sums
    for (int i = tid; i < CCHUNK * 4 * 32; i += 128) {
        int cc = i >> 7;
        int rm = i & 127;
        int r  = rm >> 5;
        int x  = rm & 31;
        const float* p = &As[cc * (4 * ASTRIDE) + r * ASTRIDE + x];
        Rs[i] = p[0] + p[1] + p[2];
    }
    if (tid < 64) {
        float s = 0.f;
#pragma unroll
        for (int k = 0; k < CCHUNK * 9; k++) s += Bs[k * 64 + tid];
        sWs[tid] = s;
    }
    __syncthreads();

    // phase 2: vertical 3-tap + channel sum -> per-pixel window sums
    if (tid < 64) {
        int y = tid >> 5, x = tid & 31;
        float s = 0.f;
#pragma unroll
        for (int cc = 0; cc < CCHUNK; cc++)
#pragma unroll
            for (int kh = 0; kh < 3; kh++)
                s += Rs[cc * 128 + (y + kh) * 32 + x];
        sAs[tid] = s;
    }
    __syncthreads();

    float acc[8][4];
#pragma unroll
    for (int i = 0; i < 8; i++)
#pragma unroll
        for (int j = 0; j < 4; j++) acc[i][j] = 0.f;

#pragma unroll 1
    for (int cc = 0; cc < CCHUNK; ++cc) {
#pragma unroll
        for (int kh = 0; kh < 3; ++kh) {
#pragma unroll
            for (int kw = 0; kw < 3; ++kw) {
                float4 bq = *(const float4*)&Bs[(cc * 9 + kh * 3 + kw) * 64 + og * 4];
                float bv[4] = {bq.x, bq.y, bq.z, bq.w};
                float av[8];
#pragma unroll
                for (int i = 0; i < 8; i++) {
                    int r = (i >> 2) + kh;
                    int q = pcol0 + 8 * (i & 3) + kw;
                    av[i] = As[cc * (4 * ASTRIDE) + r * ASTRIDE + q];
                }
#pragma unroll
                for (int i = 0; i < 8; i++) {
#pragma unroll
                    for (int j = 0; j < 4; j++) {
                        acc[i][j] += fminf(av[i], bv[j]);   // FMNMX(alu) + FADD(fma)
                    }
                }
            }
        }
    }

    // epilogue: true partial = 2*summin - sumA - sumW  (= -sum|a-w| for chunk)
    float sAv[8];
#pragma unroll
    for (int i = 0; i < 8; i++)
        sAv[i] = sAs[(i >> 2) * 32 + pcol0 + 8 * (i & 3)];
    float sWv[4];
#pragma unroll
    for (int j = 0; j < 4; j++) sWv[j] = sWs[og * 4 + j];

    float* pbase = part + ((sp * B_ + b) * C_ + og * 4) * NPIX;
#pragma unroll
    for (int j = 0; j < 4; j++) {
#pragma unroll
        for (int i = 0; i < 8; i++) {
            int y = row0 + (i >> 2);
            int x = pcol0 + 8 * (i & 3);
            pbase[j * NPIX + y * 32 + x] = fmaf(2.f, acc[i][j], -sAv[i]) - sWv[j];
        }
    }
}

// ---------------- combine adder2 partials + channel means ----------------
__global__ void k_comb_se() {
    int bc  = blockIdx.x;   // 0..255 = b*64 + c
    int tid = threadIdx.x;  // 256
    float lsum = 0.f;
    int base = bc * NPIX;
    for (int p = tid; p < NPIX; p += 256) {
        float v = 0.f;
#pragma unroll
        for (int sp = 0; sp < S_; sp++)
            v += g_p2[sp * (B_ * C_ * NPIX) + base + p];
        g_out2[base + p] = v;
        lsum += v;
    }
#pragma unroll
    for (int off = 16; off; off >>= 1)
        lsum += __shfl_xor_sync(0xffffffffu, lsum, off);
    __shared__ float ws[8];
    if ((tid & 31) == 0) ws[tid >> 5] = lsum;
    __syncthreads();
    if (tid == 0) {
        float t = 0.f;
#pragma unroll
        for (int i = 0; i < 8; i++) t += ws[i];
        g_s[bc] = t * (1.f / 1024.f);
    }
}

// ---------------- final: SE gate (per-block) + out = out2*g + x ----------
__global__ void k_final(const float* __restrict__ x,
                        const float* __restrict__ f1w, const float* __restrict__ f1b,
                        const float* __restrict__ f2w, const float* __restrict__ f2b,
                        float* __restrict__ out) {
    int bc  = blockIdx.x;            // 0..255 = b*64 + c
    int b   = bc >> 6;
    int c   = bc & 63;
    int tid = threadIdx.x;           // 256

    __shared__ float sh[64];
    __shared__ float gg;
    if (tid < 64) sh[tid] = g_s[b * 64 + tid];
    __syncthreads();
    if (tid == 0) {
        float h[4];
#pragma unroll
        for (int j = 0; j < 4; j++) {
            float a = f1b[j];
            for (int c2 = 0; c2 < 64; c2++) a += sh[c2] * f1w[j * 64 + c2];
            h[j] = fmaxf(a, 0.f);
        }
        float z = f2b[c];
#pragma unroll
        for (int j = 0; j < 4; j++) z += h[j] * f2w[c * 4 + j];
        gg = 1.f / (1.f + expf(-z));
    }
    __syncthreads();
    float g = gg;
    int base = bc * NPIX;
    for (int p = tid; p < NPIX; p += 256)
        out[base + p] = g_out2[base + p] * g + x[base + p];
}

extern "C" void kernel_launch(void* const* d_in, const int* in_sizes, int n_in,
                              void* d_out, int out_size) {
    const float* x     = (const float*)d_in[0];
    const float* bn1_g = (const float*)d_in[1];
    const float* bn1_b = (const float*)d_in[2];
    const float* bn1_m = (const float*)d_in[3];
    const float* bn1_v = (const float*)d_in[4];
    const float* w1    = (const float*)d_in[5];
    const float* bn2_g = (const float*)d_in[6];
    const float* bn2_b = (const float*)d_in[7];
    const float* bn2_m = (const float*)d_in[8];
    const float* bn2_v = (const float*)d_in[9];
    const float* w2    = (const float*)d_in[10];
    const float* fc1_w = (const float*)d_in[11];
    const float* fc1_b = (const float*)d_in[12];
    const float* fc2_w = (const float*)d_in[13];
    const float* fc2_b = (const float*)d_in[14];
    float* out = (float*)d_out;

    const int padtot = B_ * C_ * PLANE;
    dim3 ag(64, 16);

    k_bnpad<<<(padtot + 255) / 256, 256>>>(x, 0, bn1_g, bn1_b, bn1_m, bn1_v);
    k_adder<<<ag, 128>>>(0, w1);
    k_bnpad<<<(padtot + 255) / 256, 256>>>(nullptr, 1, bn2_g, bn2_b, bn2_m, bn2_v);
    k_adder<<<ag, 128>>>(1, w2);
    k_comb_se<<<256, 256>>>();
    k_final<<<256, 256>>>(x, fc1_w, fc1_b, fc2_w, fc2_b, out);
}

// round 6
// speedup vs baseline: 1.0385x; 1.0385x over previous
#include <cuda_runtime.h>
#include <cstdint>

// ---------------- problem constants ----------------
#define B_    4
#define C_    64
#define NPIX  1024            // 32*32
#define PR    34              // padded rows used (0..33)
#define PSTR  36              // padded row stride in g_a (floats)
#define PLANE (PR * PSTR)     // floats per (b,c) plane
#define S_    16              // K-split factor
#define CCHUNK 4              // channels per split
#define ASTRIDE 40            // As row stride (floats)

// ---------------- scratch (device globals) ----------------
__device__ float g_a1[B_ * C_ * PLANE];          // relu(bn1(x)), zero-padded
__device__ float g_a2[B_ * C_ * PLANE];          // relu(bn2(adder1)), zero-padded
__device__ float g_p1[S_ * B_ * C_ * NPIX];      // adder1 partials (TRUE values)
__device__ float g_p2[S_ * B_ * C_ * NPIX];      // adder2 partials (TRUE values)
__device__ float g_out2[B_ * C_ * NPIX];         // adder2 full output
__device__ float g_s[B_ * C_];                   // channel means

// ---------------- BN + ReLU into zero-padded layout ----------------
__global__ void k_bnpad(const float* __restrict__ xin, int stage,
                        const float* __restrict__ gam,
                        const float* __restrict__ bet,
                        const float* __restrict__ mu,
                        const float* __restrict__ var) {
    int idx = blockIdx.x * blockDim.x + threadIdx.x;
    const int total = B_ * C_ * PLANE;
    if (idx >= total) return;
    float* outp = stage ? g_a2 : g_a1;

    int q  = idx % PSTR;
    int t  = idx / PSTR;
    int r  = t % PR;
    int bc = t / PR;

    float val = 0.f;
    if (r >= 1 && r <= 32 && q >= 1 && q <= 32) {
        int pix = bc * NPIX + (r - 1) * 32 + (q - 1);
        int c = bc & (C_ - 1);
        float inv = gam[c] * rsqrtf(var[c] + 1e-5f);
        float bias = bet[c] - mu[c] * inv;
        float s;
        if (stage) {
            s = 0.f;
#pragma unroll
            for (int sp = 0; sp < S_; sp++)
                s += g_p1[sp * (B_ * C_ * NPIX) + pix];
        } else {
            s = xin[pix];
        }
        val = fmaxf(s * inv + bias, 0.f);
    }
    outp[idx] = val;
}

// ---------------- AdderNet conv via min-identity, K-split ----------------
// sum|a-w| = sumA + sumW - 2*sum min(a,w)
// Mainloop: FMNMX(alu) + FADD(fma); activations register-cached per cc
// (rolling 2-row window, LDS.128 loads); epilogue = STG.128.
// grid: (64 pixel-tiles, 16 k-splits); block: 128 threads (4 warps)
// thread tile = 2 rows x 4 consecutive cols (x0=4*pcol0) x 4 out-ch
__global__ __launch_bounds__(128, 7) void k_adder(int stage,
                                                  const float* __restrict__ w) {
    __shared__ __align__(16) float As[CCHUNK * 4 * ASTRIDE];  // staged a, 2.5 KB
    __shared__ __align__(16) float Bs[CCHUNK * 9 * 64];       // weights, 9 KB
    __shared__ float Rs[CCHUNK * 4 * 32];                     // 3-tap row sums
    __shared__ float sAs[64];                                 // window sums per pixel
    __shared__ float sWs[64];                                 // weight sums per out-ch

    const float* apad = stage ? g_a2 : g_a1;
    float*       part = stage ? g_p2 : g_p1;

    int tid  = threadIdx.x;
    int bx   = blockIdx.x;           // 0..63
    int sp   = blockIdx.y;           // 0..15 (k-split)
    int b    = bx >> 4;
    int row0 = (bx & 15) * 2;        // output rows row0, row0+1
    int c0   = sp * CCHUNK;

    int og    = tid >> 3;            // 0..15 -> out channels og*4..og*4+3
    int pcol0 = tid & 7;             // 0..7
    int x0    = pcol0 * 4;           // 4 consecutive output cols, 16B aligned

    // stage A: 4 channels x 4 padded rows x ASTRIDE cols (zero-fill tail)
    const float* ap = apad + (b * C_ + c0) * PLANE;
    for (int i = tid; i < CCHUNK * 4 * ASTRIDE; i += 128) {
        int cc  = i / (4 * ASTRIDE);
        int rem = i - cc * (4 * ASTRIDE);
        int r   = rem / ASTRIDE;
        int q   = rem - r * ASTRIDE;
        As[i] = (q < PSTR) ? ap[cc * PLANE + (row0 + r) * PSTR + q] : 0.f;
    }
    // stage B: weights, Bs[k][o] = w[o][c0+cc][kh][kw]
    for (int i = tid; i < CCHUNK * 9 * 64; i += 128) {
        int k  = i >> 6;                     // 0..35
        int o  = i & 63;
        int cc = k / 9;
        int t9 = k - cc * 9;
        Bs[k * 64 + o] = w[(o * C_ + c0 + cc) * 9 + t9];
    }
    __syncthreads();

    // phase 1: horizontal 3-tap row sums + per-oc weight sums
    for (int i = tid; i < CCHUNK * 4 * 32; i += 128) {
        int cc = i >> 7;
        int rm = i & 127;
        int r  = rm >> 5;
        int x  = rm & 31;
        const float* p = &As[cc * (4 * ASTRIDE) + r * ASTRIDE + x];
        Rs[i] = p[0] + p[1] + p[2];
    }
    if (tid < 64) {
        float s = 0.f;
#pragma unroll
        for (int k = 0; k < CCHUNK * 9; k++) s += Bs[k * 64 + tid];
        sWs[tid] = s;
    }
    __syncthreads();

    // phase 2: vertical 3-tap + channel sum -> per-pixel window sums
    if (tid < 64) {
        int y = tid >> 5, x = tid & 31;
        float s = 0.f;
#pragma unroll
        for (int cc = 0; cc < CCHUNK; cc++)
#pragma unroll
            for (int kh = 0; kh < 3; kh++)
                s += Rs[cc * 128 + (y + kh) * 32 + x];
        sAs[tid] = s;
    }
    __syncthreads();

    float acc[2][4][4];   // [prow][cidx][oc]
#pragma unroll
    for (int p = 0; p < 2; p++)
#pragma unroll
        for (int c = 0; c < 4; c++)
#pragma unroll
            for (int j = 0; j < 4; j++) acc[p][c][j] = 0.f;

#pragma unroll 1
    for (int cc = 0; cc < CCHUNK; ++cc) {
        const float* base = &As[cc * (4 * ASTRIDE)];
        float rows[4][6];   // rolling register window of activation rows
#pragma unroll
        for (int r = 0; r < 2; r++) {
            float4 q4 = *(const float4*)(base + r * ASTRIDE + x0);
            float2 q2 = *(const float2*)(base + r * ASTRIDE + x0 + 4);
            rows[r][0] = q4.x; rows[r][1] = q4.y; rows[r][2] = q4.z;
            rows[r][3] = q4.w; rows[r][4] = q2.x; rows[r][5] = q2.y;
        }
#pragma unroll
        for (int kh = 0; kh < 3; ++kh) {
            if (kh < 2) {   // prefetch row kh+2 (used next kh) before this kh's math
                int r = kh + 2;
                float4 q4 = *(const float4*)(base + r * ASTRIDE + x0);
                float2 q2 = *(const float2*)(base + r * ASTRIDE + x0 + 4);
                rows[r][0] = q4.x; rows[r][1] = q4.y; rows[r][2] = q4.z;
                rows[r][3] = q4.w; rows[r][4] = q2.x; rows[r][5] = q2.y;
            }
#pragma unroll
            for (int kw = 0; kw < 3; ++kw) {
                float4 bq = *(const float4*)&Bs[(cc * 9 + kh * 3 + kw) * 64 + og * 4];
                float bv[4] = {bq.x, bq.y, bq.z, bq.w};
#pragma unroll
                for (int pr = 0; pr < 2; pr++) {
#pragma unroll
                    for (int c = 0; c < 4; c++) {
                        float a = rows[pr + kh][c + kw];
#pragma unroll
                        for (int j = 0; j < 4; j++)
                            acc[pr][c][j] += fminf(a, bv[j]);  // FMNMX + FADD
                    }
                }
            }
        }
    }

    // epilogue: true partial = 2*summin - sumA - sumW ; STG.128 per (oc,row)
    float sw[4];
#pragma unroll
    for (int j = 0; j < 4; j++) sw[j] = sWs[og * 4 + j];
    float sa[2][4];
#pragma unroll
    for (int pr = 0; pr < 2; pr++)
#pragma unroll
        for (int c = 0; c < 4; c++) sa[pr][c] = sAs[pr * 32 + x0 + c];

    float* pbase = part + ((sp * B_ + b) * C_ + og * 4) * NPIX;
#pragma unroll
    for (int j = 0; j < 4; j++) {
#pragma unroll
        for (int pr = 0; pr < 2; pr++) {
            int y = row0 + pr;
            float4 v;
            v.x = fmaf(2.f, acc[pr][0][j], -sa[pr][0]) - sw[j];
            v.y = fmaf(2.f, acc[pr][1][j], -sa[pr][1]) - sw[j];
            v.z = fmaf(2.f, acc[pr][2][j], -sa[pr][2]) - sw[j];
            v.w = fmaf(2.f, acc[pr][3][j], -sa[pr][3]) - sw[j];
            *(float4*)&pbase[j * NPIX + y * 32 + x0] = v;
        }
    }
}

// ---------------- combine adder2 partials + channel means ----------------
__global__ void k_comb_se() {
    int bc  = blockIdx.x;   // 0..255 = b*64 + c
    int tid = threadIdx.x;  // 256
    float lsum = 0.f;
    int base = bc * NPIX;
    for (int p = tid; p < NPIX; p += 256) {
        float v = 0.f;
#pragma unroll
        for (int sp = 0; sp < S_; sp++)
            v += g_p2[sp * (B_ * C_ * NPIX) + base + p];
        g_out2[base + p] = v;
        lsum += v;
    }
#pragma unroll
    for (int off = 16; off; off >>= 1)
        lsum += __shfl_xor_sync(0xffffffffu, lsum, off);
    __shared__ float ws[8];
    if ((tid & 31) == 0) ws[tid >> 5] = lsum;
    __syncthreads();
    if (tid == 0) {
        float t = 0.f;
#pragma unroll
        for (int i = 0; i < 8; i++) t += ws[i];
        g_s[bc] = t * (1.f / 1024.f);
    }
}

// ---------------- final: SE gate (per-block) + out = out2*g + x ----------
__global__ void k_final(const float* __restrict__ x,
                        const float* __restrict__ f1w, const float* __restrict__ f1b,
                        const float* __restrict__ f2w, const float* __restrict__ f2b,
                        float* __restrict__ out) {
    int bc  = blockIdx.x;            // 0..255 = b*64 + c
    int b   = bc >> 6;
    int c   = bc & 63;
    int tid = threadIdx.x;           // 256

    __shared__ float sh[64];
    __shared__ float gg;
    if (tid < 64) sh[tid] = g_s[b * 64 + tid];
    __syncthreads();
    if (tid == 0) {
        float h[4];
#pragma unroll
        for (int j = 0; j < 4; j++) {
            float a = f1b[j];
            for (int c2 = 0; c2 < 64; c2++) a += sh[c2] * f1w[j * 64 + c2];
            h[j] = fmaxf(a, 0.f);
        }
        float z = f2b[c];
#pragma unroll
        for (int j = 0; j < 4; j++) z += h[j] * f2w[c * 4 + j];
        gg = 1.f / (1.f + expf(-z));
    }
    __syncthreads();
    float g = gg;
    int base = bc * NPIX;
    for (int p = tid; p < NPIX; p += 256)
        out[base + p] = g_out2[base + p] * g + x[base + p];
}

extern "C" void kernel_launch(void* const* d_in, const int* in_sizes, int n_in,
                              void* d_out, int out_size) {
    const float* x     = (const float*)d_in[0];
    const float* bn1_g = (const float*)d_in[1];
    const float* bn1_b = (const float*)d_in[2];
    const float* bn1_m = (const float*)d_in[3];
    const float* bn1_v = (const float*)d_in[4];
    const float* w1    = (const float*)d_in[5];
    const float* bn2_g = (const float*)d_in[6];
    const float* bn2_b = (const float*)d_in[7];
    const float* bn2_m = (const float*)d_in[8];
    const float* bn2_v = (const float*)d_in[9];
    const float* w2    = (const float*)d_in[10];
    const float* fc1_w = (const float*)d_in[11];
    const float* fc1_b = (const float*)d_in[12];
    const float* fc2_w = (const float*)d_in[13];
    const float* fc2_b = (const float*)d_in[14];
    float* out = (float*)d_out;

    const int padtot = B_ * C_ * PLANE;
    dim3 ag(64, 16);

    k_bnpad<<<(padtot + 255) / 256, 256>>>(x, 0, bn1_g, bn1_b, bn1_m, bn1_v);
    k_adder<<<ag, 128>>>(0, w1);
    k_bnpad<<<(padtot + 255) / 256, 256>>>(nullptr, 1, bn2_g, bn2_b, bn2_m, bn2_v);
    k_adder<<<ag, 128>>>(1, w2);
    k_comb_se<<<256, 256>>>();
    k_final<<<256, 256>>>(x, fc1_w, fc1_b, fc2_w, fc2_b, out);
}

// round 7
// speedup vs baseline: 1.3067x; 1.2582x over previous
#include <cuda_runtime.h>
#include <cstdint>

// ---------------- problem constants ----------------
#define B_    4
#define C_    64
#define NPIX  1024            // 32*32
#define PR    34              // padded rows used (0..33)
#define PSTR  36              // padded row stride in g_a (floats)
#define PLANE (PR * PSTR)     // floats per (b,c) plane
#define S_    16              // K-split factor
#define CCHUNK 4              // channels per split
#define ASTRIDE 40            // As row stride (floats)
#define KW_   36              // k-steps per split (CCHUNK*9)

// ---------------- scratch (device globals) ----------------
__device__ float g_a1[B_ * C_ * PLANE];          // relu(bn1(x)), zero-padded
__device__ float g_a2[B_ * C_ * PLANE];          // relu(bn2(adder1)), zero-padded
__device__ float g_p1[S_ * B_ * C_ * NPIX];      // adder1 partials (TRUE values)
__device__ float g_p2[S_ * B_ * C_ * NPIX];      // adder2 partials (TRUE values)
__device__ float g_out2[B_ * C_ * NPIX];         // adder2 full output
__device__ float g_s[B_ * C_];                   // channel means
__device__ __align__(16) float g_wr[2 * S_ * KW_ * 64];  // reordered weights

// ---------------- weight reorder: w[(o*C+c0+cc)*9+t9] -> [st][sp][k][o] ---
__global__ void k_wprep(const float* __restrict__ w1,
                        const float* __restrict__ w2) {
    int idx = blockIdx.x * blockDim.x + threadIdx.x;
    if (idx >= 2 * S_ * KW_ * 64) return;
    int o  = idx & 63;
    int t  = idx >> 6;
    int k  = t % KW_;
    int sp = (t / KW_) % S_;
    int st = t / (KW_ * S_);
    int cc = k / 9;
    int t9 = k - cc * 9;
    const float* w = st ? w2 : w1;
    g_wr[idx] = w[(o * C_ + sp * CCHUNK + cc) * 9 + t9];
}

// ---------------- BN + ReLU into zero-padded layout ----------------
__global__ void k_bnpad(const float* __restrict__ xin, int stage,
                        const float* __restrict__ gam,
                        const float* __restrict__ bet,
                        const float* __restrict__ mu,
                        const float* __restrict__ var) {
    int idx = blockIdx.x * blockDim.x + threadIdx.x;
    const int total = B_ * C_ * PLANE;
    if (idx >= total) return;
    float* outp = stage ? g_a2 : g_a1;

    int q  = idx % PSTR;
    int t  = idx / PSTR;
    int r  = t % PR;
    int bc = t / PR;

    float val = 0.f;
    if (r >= 1 && r <= 32 && q >= 1 && q <= 32) {
        int pix = bc * NPIX + (r - 1) * 32 + (q - 1);
        int c = bc & (C_ - 1);
        float inv = gam[c] * rsqrtf(var[c] + 1e-5f);
        float bias = bet[c] - mu[c] * inv;
        float s;
        if (stage) {
            s = 0.f;
#pragma unroll
            for (int sp = 0; sp < S_; sp++)
                s += g_p1[sp * (B_ * C_ * NPIX) + pix];
        } else {
            s = xin[pix];
        }
        val = fmaxf(s * inv + bias, 0.f);
    }
    outp[idx] = val;
}

// ---------------- AdderNet conv via min-identity, K-split ----------------
// sum|a-w| = sumA + sumW - 2*sum min(a,w)
// Weights pre-reordered (k_wprep) -> staging is a coalesced float4 copy.
// grid: (64 pixel-tiles, 16 k-splits); block: 128 threads (4 warps)
// thread tile = 2 rows x 4 consecutive cols (x0=4*pcol0) x 4 out-ch
__global__ __launch_bounds__(128, 7) void k_adder(int stage) {
    __shared__ __align__(16) float As[CCHUNK * 4 * ASTRIDE];  // staged a
    __shared__ __align__(16) float Bs[KW_ * 64];              // weights, 9 KB
    __shared__ float Rs[CCHUNK * 4 * 32];                     // 3-tap row sums
    __shared__ float sAs[64];                                 // window sums per pixel
    __shared__ float sWs[64];                                 // weight sums per out-ch

    const float* apad = stage ? g_a2 : g_a1;
    float*       part = stage ? g_p2 : g_p1;

    int tid  = threadIdx.x;
    int bx   = blockIdx.x;           // 0..63
    int sp   = blockIdx.y;           // 0..15 (k-split)
    int b    = bx >> 4;
    int row0 = (bx & 15) * 2;        // output rows row0, row0+1
    int c0   = sp * CCHUNK;

    int og    = tid >> 3;            // 0..15 -> out channels og*4..og*4+3
    int pcol0 = tid & 7;             // 0..7
    int x0    = pcol0 * 4;           // 4 consecutive output cols, 16B aligned

    // stage A: 4 channels x 4 padded rows x ASTRIDE cols (zero-fill tail)
    const float* ap = apad + (b * C_ + c0) * PLANE;
    for (int i = tid; i < CCHUNK * 4 * ASTRIDE; i += 128) {
        int cc  = i / (4 * ASTRIDE);
        int rem = i - cc * (4 * ASTRIDE);
        int r   = rem / ASTRIDE;
        int q   = rem - r * ASTRIDE;
        As[i] = (q < PSTR) ? ap[cc * PLANE + (row0 + r) * PSTR + q] : 0.f;
    }
    // stage B: coalesced float4 copy from reordered weights
    {
        const float4* wr4 = (const float4*)(g_wr + (stage * S_ + sp) * KW_ * 64);
        float4* Bs4 = (float4*)Bs;
        for (int i = tid; i < KW_ * 16; i += 128)   // 36*64/4 = 576
            Bs4[i] = wr4[i];
    }
    __syncthreads();

    // phase 1: horizontal 3-tap row sums + per-oc weight sums
    for (int i = tid; i < CCHUNK * 4 * 32; i += 128) {
        int cc = i >> 7;
        int rm = i & 127;
        int r  = rm >> 5;
        int x  = rm & 31;
        const float* p = &As[cc * (4 * ASTRIDE) + r * ASTRIDE + x];
        Rs[i] = p[0] + p[1] + p[2];
    }
    if (tid < 64) {
        float s = 0.f;
#pragma unroll
        for (int k = 0; k < KW_; k++) s += Bs[k * 64 + tid];
        sWs[tid] = s;
    }
    __syncthreads();

    // phase 2: vertical 3-tap + channel sum -> per-pixel window sums
    if (tid < 64) {
        int y = tid >> 5, x = tid & 31;
        float s = 0.f;
#pragma unroll
        for (int cc = 0; cc < CCHUNK; cc++)
#pragma unroll
            for (int kh = 0; kh < 3; kh++)
                s += Rs[cc * 128 + (y + kh) * 32 + x];
        sAs[tid] = s;
    }
    __syncthreads();

    float acc[2][4][4];   // [prow][cidx][oc]
#pragma unroll
    for (int p = 0; p < 2; p++)
#pragma unroll
        for (int c = 0; c < 4; c++)
#pragma unroll
            for (int j = 0; j < 4; j++) acc[p][c][j] = 0.f;

#pragma unroll 1
    for (int cc = 0; cc < CCHUNK; ++cc) {
        const float* base = &As[cc * (4 * ASTRIDE)];
        float rows[4][6];   // rolling register window of activation rows
#pragma unroll
        for (int r = 0; r < 2; r++) {
            float4 q4 = *(const float4*)(base + r * ASTRIDE + x0);
            float2 q2 = *(const float2*)(base + r * ASTRIDE + x0 + 4);
            rows[r][0] = q4.x; rows[r][1] = q4.y; rows[r][2] = q4.z;
            rows[r][3] = q4.w; rows[r][4] = q2.x; rows[r][5] = q2.y;
        }
#pragma unroll
        for (int kh = 0; kh < 3; ++kh) {
            if (kh < 2) {   // prefetch row kh+2 before this kh's math
                int r = kh + 2;
                float4 q4 = *(const float4*)(base + r * ASTRIDE + x0);
                float2 q2 = *(const float2*)(base + r * ASTRIDE + x0 + 4);
                rows[r][0] = q4.x; rows[r][1] = q4.y; rows[r][2] = q4.z;
                rows[r][3] = q4.w; rows[r][4] = q2.x; rows[r][5] = q2.y;
            }
#pragma unroll
            for (int kw = 0; kw < 3; ++kw) {
                float4 bq = *(const float4*)&Bs[(cc * 9 + kh * 3 + kw) * 64 + og * 4];
                float bv[4] = {bq.x, bq.y, bq.z, bq.w};
#pragma unroll
                for (int pr = 0; pr < 2; pr++) {
#pragma unroll
                    for (int c = 0; c < 4; c++) {
                        float a = rows[pr + kh][c + kw];
#pragma unroll
                        for (int j = 0; j < 4; j++)
                            acc[pr][c][j] += fminf(a, bv[j]);  // FMNMX + FADD
                    }
                }
            }
        }
    }

    // epilogue: true partial = 2*summin - sumA - sumW ; STG.128 per (oc,row)
    float sw[4];
#pragma unroll
    for (int j = 0; j < 4; j++) sw[j] = sWs[og * 4 + j];
    float sa[2][4];
#pragma unroll
    for (int pr = 0; pr < 2; pr++)
#pragma unroll
        for (int c = 0; c < 4; c++) sa[pr][c] = sAs[pr * 32 + x0 + c];

    float* pbase = part + ((sp * B_ + b) * C_ + og * 4) * NPIX;
#pragma unroll
    for (int j = 0; j < 4; j++) {
#pragma unroll
        for (int pr = 0; pr < 2; pr++) {
            int y = row0 + pr;
            float4 v;
            v.x = fmaf(2.f, acc[pr][0][j], -sa[pr][0]) - sw[j];
            v.y = fmaf(2.f, acc[pr][1][j], -sa[pr][1]) - sw[j];
            v.z = fmaf(2.f, acc[pr][2][j], -sa[pr][2]) - sw[j];
            v.w = fmaf(2.f, acc[pr][3][j], -sa[pr][3]) - sw[j];
            *(float4*)&pbase[j * NPIX + y * 32 + x0] = v;
        }
    }
}

// ---------------- combine adder2 partials + channel means ----------------
__global__ void k_comb_se() {
    int bc  = blockIdx.x;   // 0..255 = b*64 + c
    int tid = threadIdx.x;  // 256
    float lsum = 0.f;
    int base = bc * NPIX;
    for (int p = tid; p < NPIX; p += 256) {
        float v = 0.f;
#pragma unroll
        for (int sp = 0; sp < S_; sp++)
            v += g_p2[sp * (B_ * C_ * NPIX) + base + p];
        g_out2[base + p] = v;
        lsum += v;
    }
#pragma unroll
    for (int off = 16; off; off >>= 1)
        lsum += __shfl_xor_sync(0xffffffffu, lsum, off);
    __shared__ float ws[8];
    if ((tid & 31) == 0) ws[tid >> 5] = lsum;
    __syncthreads();
    if (tid == 0) {
        float t = 0.f;
#pragma unroll
        for (int i = 0; i < 8; i++) t += ws[i];
        g_s[bc] = t * (1.f / 1024.f);
    }
}

// ---------------- final: SE gate (per-block) + out = out2*g + x ----------
__global__ void k_final(const float* __restrict__ x,
                        const float* __restrict__ f1w, const float* __restrict__ f1b,
                        const float* __restrict__ f2w, const float* __restrict__ f2b,
                        float* __restrict__ out) {
    int bc  = blockIdx.x;            // 0..255 = b*64 + c
    int b   = bc >> 6;
    int c   = bc & 63;
    int tid = threadIdx.x;           // 256

    __shared__ float sh[64];
    __shared__ float gg;
    if (tid < 64) sh[tid] = g_s[b * 64 + tid];
    __syncthreads();
    if (tid == 0) {
        float h[4];
#pragma unroll
        for (int j = 0; j < 4; j++) {
            float a = f1b[j];
            for (int c2 = 0; c2 < 64; c2++) a += sh[c2] * f1w[j * 64 + c2];
            h[j] = fmaxf(a, 0.f);
        }
        float z = f2b[c];
#pragma unroll
        for (int j = 0; j < 4; j++) z += h[j] * f2w[c * 4 + j];
        gg = 1.f / (1.f + expf(-z));
    }
    __syncthreads();
    float g = gg;
    int base = bc * NPIX;
    for (int p = tid; p < NPIX; p += 256)
        out[base + p] = g_out2[base + p] * g + x[base + p];
}

extern "C" void kernel_launch(void* const* d_in, const int* in_sizes, int n_in,
                              void* d_out, int out_size) {
    const float* x     = (const float*)d_in[0];
    const float* bn1_g = (const float*)d_in[1];
    const float* bn1_b = (const float*)d_in[2];
    const float* bn1_m = (const float*)d_in[3];
    const float* bn1_v = (const float*)d_in[4];
    const float* w1    = (const float*)d_in[5];
    const float* bn2_g = (const float*)d_in[6];
    const float* bn2_b = (const float*)d_in[7];
    const float* bn2_m = (const float*)d_in[8];
    const float* bn2_v = (const float*)d_in[9];
    const float* w2    = (const float*)d_in[10];
    const float* fc1_w = (const float*)d_in[11];
    const float* fc1_b = (const float*)d_in[12];
    const float* fc2_w = (const float*)d_in[13];
    const float* fc2_b = (const float*)d_in[14];
    float* out = (float*)d_out;

    const int padtot = B_ * C_ * PLANE;
    const int wtot   = 2 * S_ * KW_ * 64;
    dim3 ag(64, 16);

    k_wprep<<<(wtot + 255) / 256, 256>>>(w1, w2);
    k_bnpad<<<(padtot + 255) / 256, 256>>>(x, 0, bn1_g, bn1_b, bn1_m, bn1_v);
    k_adder<<<ag, 128>>>(0);
    k_bnpad<<<(padtot + 255) / 256, 256>>>(nullptr, 1, bn2_g, bn2_b, bn2_m, bn2_v);
    k_adder<<<ag, 128>>>(1);
    k_comb_se<<<256, 256>>>();
    k_final<<<256, 256>>>(x, fc1_w, fc1_b, fc2_w, fc2_b, out);
}